// round 2
// baseline (speedup 1.0000x reference)
#include <cuda_runtime.h>

// Malvar-He-Cutler demosaic, GB300 (sm_103a). Round 2:
//  - vertical-basis accumulators (a=v0+v4, b=v1+v3, c=v2 per column) -> 48 accum regs
//  - quad origin at base_c = 4t-2 so the 8-col window [base_c-2, base_c+5] is
//    exactly two aligned float4 loads per row (was 3)
//  - float2 streaming stores (8B-aligned), __launch_bounds__(256,3) for occupancy

__device__ __forceinline__ float clip01(float v) {
    return fminf(fmaxf(v, 0.0f), 1.0f);
}

__device__ __forceinline__ int refl(int i, int n) {
    i = (i < 0) ? -i : i;
    return (i >= n) ? (2 * n - 2 - i) : i;
}

__global__ void __launch_bounds__(256, 3)
demosaic_kernel(const float* __restrict__ x, float* __restrict__ out,
                int H, int W)
{
    // Thread handles 2 rows x 4 cols; base_c = 4t-2 (even, window float4-aligned).
    const int t      = blockIdx.x * blockDim.x + threadIdx.x;
    const int base_c = t * 4 - 2;
    const int base_r = (blockIdx.y * blockDim.y + threadIdx.y) * 2;
    if (base_c >= W || base_r >= H) return;

    // Vertical bases over local cols i=0..7 (global col = base_c-2+i).
    // Output row0 (j=2): a=v0+v4, b=v1+v3, c=v2
    // Output row1 (j=3): A=v1+v5, B=v2+v4, C=v3
    float a[8], b[8], c[8], A[8], B[8], C[8];

    const bool fast = (base_r >= 2) & (base_r + 3 < H) & (base_c >= 2) & (base_c + 5 < W);

#define ACCUM(J)                                                        \
    _Pragma("unroll")                                                   \
    for (int i = 0; i < 8; ++i) {                                       \
        if (J == 0)      { a[i] = r[i]; }                               \
        else if (J == 1) { b[i] = r[i]; A[i] = r[i]; }                  \
        else if (J == 2) { c[i] = r[i]; B[i] = r[i]; }                  \
        else if (J == 3) { C[i] = r[i]; b[i] += r[i]; }                 \
        else if (J == 4) { a[i] += r[i]; B[i] += r[i]; }                \
        else             { A[i] += r[i]; }                              \
    }

    if (fast) {
        const float* rp = x + (size_t)(base_r - 2) * W + (base_c - 2);
        #pragma unroll
        for (int j = 0; j < 6; ++j) {
            float4 u = *reinterpret_cast<const float4*>(rp);
            float4 w = *reinterpret_cast<const float4*>(rp + 4);
            rp += W;
            float r[8] = {u.x, u.y, u.z, u.w, w.x, w.y, w.z, w.w};
            ACCUM(j)
        }
    } else {
        #pragma unroll
        for (int j = 0; j < 6; ++j) {
            const int rr = refl(base_r - 2 + j, H);
            const float* rp = x + (size_t)rr * W;
            float r[8];
            #pragma unroll
            for (int i = 0; i < 8; ++i)
                r[i] = rp[refl(base_c - 2 + i, W)];
            ACCUM(j)
        }
    }
#undef ACCUM

    // Stencils in basis form (weights /8):
    //  GI  = (4c + 2(b + c_l + c_r) - (a + c_ll + c_rr)) / 8
    //  RGR = (5c + 4(c_l+c_r) - (c_ll+c_rr) + 0.5a - (b_l+b_r)) / 8   [strong horiz]
    //  RGV = (5c + 4b - a + 0.5(c_ll+c_rr) - (b_l+b_r)) / 8           [strong vert]
    //  RB  = (6c + 2(b_l+b_r) - 1.5(a + c_ll + c_rr)) / 8             [diagonal]

    float o0[12], o1[12];
    #pragma unroll
    for (int p = 0; p < 4; ++p) {
        const int q = p + 2;
        // ---- row 0 (even row): basis (a,b,c) ----
        {
            float cc = c[q], bb = b[q], aa = a[q];
            float s1 = c[q-1] + c[q+1];
            float s2 = c[q-2] + c[q+2];
            float s3 = b[q-1] + b[q+1];
            float gi  = 0.125f * (4.0f*cc + 2.0f*(bb + s1) - (aa + s2));
            float rgr = 0.125f * (5.0f*cc + 4.0f*s1 - s2 + 0.5f*aa - s3);
            float rgv = 0.125f * (5.0f*cc + 4.0f*bb - aa + 0.5f*s2 - s3);
            float rb  = 0.125f * (6.0f*cc + 2.0f*s3 - 1.5f*(aa + s2));
            if ((p & 1) == 0) {  // R site (even col)
                o0[3*p+0] = clip01(cc);
                o0[3*p+1] = clip01(gi);
                o0[3*p+2] = clip01(rb);
            } else {             // Gr site
                o0[3*p+0] = clip01(rgr);
                o0[3*p+1] = clip01(cc);
                o0[3*p+2] = clip01(rgv);
            }
        }
        // ---- row 1 (odd row): basis (A,B,C) ----
        {
            float cc = C[q], bb = B[q], aa = A[q];
            float s1 = C[q-1] + C[q+1];
            float s2 = C[q-2] + C[q+2];
            float s3 = B[q-1] + B[q+1];
            float gi  = 0.125f * (4.0f*cc + 2.0f*(bb + s1) - (aa + s2));
            float rgr = 0.125f * (5.0f*cc + 4.0f*s1 - s2 + 0.5f*aa - s3);
            float rgv = 0.125f * (5.0f*cc + 4.0f*bb - aa + 0.5f*s2 - s3);
            float rb  = 0.125f * (6.0f*cc + 2.0f*s3 - 1.5f*(aa + s2));
            if ((p & 1) == 0) {  // Gb site (even col, odd row)
                o1[3*p+0] = clip01(rgv);
                o1[3*p+1] = clip01(cc);
                o1[3*p+2] = clip01(rgr);
            } else {             // B site
                o1[3*p+0] = clip01(rb);
                o1[3*p+1] = clip01(gi);
                o1[3*p+2] = clip01(cc);
            }
        }
    }

    if (base_c >= 0 && base_c + 4 <= W) {
        float* p0 = out + ((size_t)base_r * W + base_c) * 3;
        float* p1 = p0 + (size_t)W * 3;
        // base_c = 4t-2 -> float offset base_c*3 even -> 8-byte aligned.
        float2* q0 = reinterpret_cast<float2*>(p0);
        float2* q1 = reinterpret_cast<float2*>(p1);
        #pragma unroll
        for (int k = 0; k < 6; ++k) __stcs(q0 + k, make_float2(o0[2*k], o0[2*k+1]));
        #pragma unroll
        for (int k = 0; k < 6; ++k) __stcs(q1 + k, make_float2(o1[2*k], o1[2*k+1]));
    } else {
        #pragma unroll
        for (int p = 0; p < 4; ++p) {
            const int col = base_c + p;
            if (col < 0 || col >= W) continue;
            float* q = out + ((size_t)base_r * W + col) * 3;
            q[0] = o0[3*p]; q[1] = o0[3*p+1]; q[2] = o0[3*p+2];
            if (base_r + 1 < H) {
                float* q2 = out + ((size_t)(base_r + 1) * W + col) * 3;
                q2[0] = o1[3*p]; q2[1] = o1[3*p+1]; q2[2] = o1[3*p+2];
            }
        }
    }
}

extern "C" void kernel_launch(void* const* d_in, const int* in_sizes, int n_in,
                              void* d_out, int out_size)
{
    const float* x = (const float*)d_in[0];
    long nx = in_sizes[0];
    if (n_in > 1 && in_sizes[1] > in_sizes[0]) {  // defensive: pick the big tensor as x
        x = (const float*)d_in[1];
        nx = in_sizes[1];
    }

    const int W = 6144;
    const int H = (int)(nx / W);

    const int quads_x = W / 4 + 1;                 // base_c = 4t-2 covers cols [-2, W+1]
    dim3 block(32, 8);
    dim3 grid((unsigned)((quads_x + 31) / 32),
              (unsigned)((H / 2 + 7) / 8));

    demosaic_kernel<<<grid, block>>>(x, (float*)d_out, H, W);
}

// round 3
// speedup vs baseline: 1.6035x; 1.6035x over previous
#include <cuda_runtime.h>

// Malvar-He-Cutler demosaic, GB300 (sm_103a). Round 3: smem-tiled.
// CTA stages a (32+4) x (128+8) fp32 tile once (coalesced, each input byte
// fetched once), threads compute from smem with conflict-free LDS.128 and
// write aligned float4 streaming stores.

#define TR 32
#define TC 128
#define SR (TR + 4)    // 36 rows  (halo 2 each side)
#define SC (TC + 8)    // 136 cols (halo 2 each side + pad to float4 multiple)

__device__ __forceinline__ float clip01(float v) {
    return fminf(fmaxf(v, 0.0f), 1.0f);
}
__device__ __forceinline__ int refl(int i, int n) {
    i = (i < 0) ? -i : i;
    return (i >= n) ? (2 * n - 2 - i) : i;
}

__global__ void __launch_bounds__(256, 4)
demosaic_kernel(const float* __restrict__ x, float* __restrict__ out,
                int H, int W)
{
    __shared__ __align__(16) float s[SR][SC];

    const int tid     = threadIdx.x;
    const int tile_c0 = blockIdx.x * TC;
    const int tile_r0 = blockIdx.y * TR;

    // ---- Stage tile into smem (coalesced; reflect only on border tiles) ----
    const int r0 = tile_r0 - 2;
    const int c0 = tile_c0 - 2;
    const bool interior = (r0 >= 0) & (r0 + SR <= H) & (c0 >= 0) & (c0 + SC <= W);

    if (interior) {
        #pragma unroll
        for (int k = 0; k < (SR * SC + 255) / 256; ++k) {
            const int idx = tid + k * 256;
            if (idx < SR * SC) {
                const int lr = idx / SC;
                const int lc = idx - lr * SC;
                s[lr][lc] = x[(size_t)(r0 + lr) * W + (c0 + lc)];
            }
        }
    } else {
        for (int idx = tid; idx < SR * SC; idx += 256) {
            const int lr = idx / SC;
            const int lc = idx - lr * SC;
            const int gr = refl(r0 + lr, H);
            const int gc = refl(c0 + lc, W);
            s[lr][lc] = x[(size_t)gr * W + gc];
        }
    }
    __syncthreads();

    // ---- Compute: thread handles 4 output rows x 4 cols (two 2x4 quads) ----
    // tx in [0,32): col quad -> local out cols 4*tx.  ty in [0,8): row pair.
    const int tx = tid & 31;
    const int ty = tid >> 5;
    const int cbase = 4 * tx;  // smem col of window start (out col local 4tx - 2 maps here)

    #pragma unroll
    for (int qq = 0; qq < 2; ++qq) {
        const int rp = ty + qq * 8;  // row-pair index 0..15
        #pragma unroll
        for (int sub = 0; sub < 2; ++sub) {
            const int lr_out = 2 * rp + sub;   // local output row
            const int j0 = lr_out + 2;         // smem row of the output row
            // Vertical bases over 8 cols: a = v[-2]+v[+2], b = v[-1]+v[+1], c = v[0]
            float a[8], b[8], c[8];
            #pragma unroll
            for (int dj = -2; dj <= 2; ++dj) {
                const float4 u = *reinterpret_cast<const float4*>(&s[j0 + dj][cbase]);
                const float4 w = *reinterpret_cast<const float4*>(&s[j0 + dj][cbase + 4]);
                const float r[8] = {u.x, u.y, u.z, u.w, w.x, w.y, w.z, w.w};
                #pragma unroll
                for (int i = 0; i < 8; ++i) {
                    if (dj == -2)      a[i]  = r[i];
                    else if (dj == -1) b[i]  = r[i];
                    else if (dj == 0)  c[i]  = r[i];
                    else if (dj == 1)  b[i] += r[i];
                    else               a[i] += r[i];
                }
            }

            float o[12];
            #pragma unroll
            for (int p = 0; p < 4; ++p) {
                const int q = p + 2;
                const float cc = c[q], bb = b[q], aa = a[q];
                const float s1 = c[q-1] + c[q+1];
                const float s2 = c[q-2] + c[q+2];
                const float s3 = b[q-1] + b[q+1];
                const float gi  = 0.125f * (4.0f*cc + 2.0f*(bb + s1) - (aa + s2));
                const float rgr = 0.125f * (5.0f*cc + 4.0f*s1 - s2 + 0.5f*aa - s3);
                const float rgv = 0.125f * (5.0f*cc + 4.0f*bb - aa + 0.5f*s2 - s3);
                const float rb  = 0.125f * (6.0f*cc + 2.0f*s3 - 1.5f*(aa + s2));
                float R, G, B;
                if (sub == 0) {           // even global row
                    if ((p & 1) == 0) { R = cc;  G = gi; B = rb;  }   // R site
                    else              { R = rgr; G = cc; B = rgv; }   // Gr site
                } else {                  // odd global row
                    if ((p & 1) == 0) { R = rgv; G = cc; B = rgr; }   // Gb site
                    else              { R = rb;  G = gi; B = cc;  }   // B site
                }
                o[3*p+0] = clip01(R);
                o[3*p+1] = clip01(G);
                o[3*p+2] = clip01(B);
            }

            const int gr = tile_r0 + lr_out;
            const int gc = tile_c0 + cbase;
            if (gr < H && gc + 4 <= W) {
                // gc multiple of 4 -> float offset gc*3 multiple of 12 -> 16B aligned.
                float4* dst = reinterpret_cast<float4*>(out + ((size_t)gr * W + gc) * 3);
                __stcs(dst + 0, make_float4(o[0], o[1], o[2],  o[3]));
                __stcs(dst + 1, make_float4(o[4], o[5], o[6],  o[7]));
                __stcs(dst + 2, make_float4(o[8], o[9], o[10], o[11]));
            } else if (gr < H) {
                #pragma unroll
                for (int p = 0; p < 4; ++p) {
                    if (gc + p < W) {
                        float* q2 = out + ((size_t)gr * W + gc + p) * 3;
                        q2[0] = o[3*p]; q2[1] = o[3*p+1]; q2[2] = o[3*p+2];
                    }
                }
            }
        }
    }
}

extern "C" void kernel_launch(void* const* d_in, const int* in_sizes, int n_in,
                              void* d_out, int out_size)
{
    const float* x = (const float*)d_in[0];
    long nx = in_sizes[0];
    if (n_in > 1 && in_sizes[1] > in_sizes[0]) {  // defensive: pick the big tensor as x
        x = (const float*)d_in[1];
        nx = in_sizes[1];
    }

    const int W = 6144;
    const int H = (int)(nx / W);

    dim3 block(256);
    dim3 grid((unsigned)((W + TC - 1) / TC), (unsigned)((H + TR - 1) / TR));

    demosaic_kernel<<<grid, block>>>(x, (float*)d_out, H, W);
}